// round 4
// baseline (speedup 1.0000x reference)
#include <cuda_runtime.h>

// Problem constants
#define NB    32768
#define NSTEP 99
#define TT    100
#define NBLK  128
#define NTHR  256
#define DTs   0.01f
#define EPSs  1e-6f
#define INVB  (1.0f/32768.0f)

// param smem offsets
#define OW1  0
#define OW2  72
#define OW3  216
#define OB3  288
#define OG0  294
#define OBE0 300
#define OG1  306
#define OBE1 318
#define OG2  330
#define OBE2 342
#define OG3  354
#define OBE3 360

static_assert(NBLK * NTHR == NB, "grid must cover batch exactly");

__device__ unsigned g_bar;
__device__ float g_part[2][NBLK][28];

__constant__ int cK[21] = {0,0,0,0,0,0, 1,1,1,1,1, 2,2,2,2, 3,3,3, 4,4, 5};
__constant__ int cL[21] = {0,1,2,3,4,5, 1,2,3,4,5, 2,3,4,5, 3,4,5, 4,5, 5};

struct SM {
    float sp[368];          // per-step params
    float sred[8][28];      // warp partials
    float ssum[28];         // combined batch sums
    float sc[6];            // shift (previous step's zin mean)
    float smdev[6];
    float sM[6];            // current zin mean
    float sCov[21];
    float sA0[6];           // g0 * rsqrt(var0+eps)
    float sMean1[12], sInv1[12];
    float sMean2[12], sInv2[12];
    float sMean3[6],  sInv3[6];
};

__device__ __forceinline__ int cidx(int k, int l) {   // pair index, k<=l
    return 6*k - (k*(k-1))/2 + (l - k);
}

__device__ __forceinline__ float wred(float v) {
    v += __shfl_xor_sync(0xffffffffu, v, 16);
    v += __shfl_xor_sync(0xffffffffu, v, 8);
    v += __shfl_xor_sync(0xffffffffu, v, 4);
    v += __shfl_xor_sync(0xffffffffu, v, 2);
    v += __shfl_xor_sync(0xffffffffu, v, 1);
    return v;
}

// deterministic block-level partial reduction -> g_part[buf][block][0..N)
template<int N>
__device__ __forceinline__ void block_part(float* v, int buf, int tid, SM& sm) {
    int wid = tid >> 5, lane = tid & 31;
#pragma unroll
    for (int i = 0; i < N; i++) v[i] = wred(v[i]);
    if (lane == 0) {
#pragma unroll
        for (int i = 0; i < N; i++) sm.sred[wid][i] = v[i];
    }
    __syncthreads();
    if (tid < N) {
        float s = 0.f;
#pragma unroll
        for (int w = 0; w < 8; w++) s += sm.sred[w][tid];
        __stcg(&g_part[buf][blockIdx.x][tid], s);
    }
}

// software grid barrier. The kernel is launched with
// cudaLaunchCooperativeKernel, so the driver GUARANTEES all NBLK blocks are
// co-resident (or fails the launch with an explicit error instead of
// hanging). Same fence/arrive/acquire-poll pattern as cg::grid.sync().
__device__ __forceinline__ void grid_barrier(unsigned target) {
    __syncthreads();
    if (threadIdx.x == 0) {
        __threadfence();
        atomicAdd(&g_bar, 1u);
        unsigned v;
        for (;;) {
            asm volatile("ld.acquire.gpu.u32 %0, [%1];"
                         : "=r"(v) : "l"(&g_bar) : "memory");
            if (v >= target) break;
            __nanosleep(20);
        }
    }
    __syncthreads();
}

// deterministic combine of all 128 block partials -> sm.ssum (every block)
template<int N>
__device__ __forceinline__ void combine(int buf, int tid, SM& sm) {
    int wid = tid >> 5, lane = tid & 31;
#pragma unroll
    for (int v = wid; v < N; v += 8) {
        float s = __ldcg(&g_part[buf][lane      ][v])
                + __ldcg(&g_part[buf][lane + 32 ][v])
                + __ldcg(&g_part[buf][lane + 64 ][v])
                + __ldcg(&g_part[buf][lane + 96 ][v]);
        s = wred(s);
        if (lane == 0) sm.ssum[v] = s;
    }
    __syncthreads();
}

__global__ void init_bar() { g_bar = 0u; }

__global__ void __launch_bounds__(NTHR)
sde_kernel(const float* __restrict__ W,  const float* __restrict__ S,
           const float* __restrict__ y0i, const float* __restrict__ y1i,
           const float* __restrict__ z0i, const float* __restrict__ z1i,
           const float* __restrict__ W1, const float* __restrict__ W2,
           const float* __restrict__ W3, const float* __restrict__ b3,
           const float* __restrict__ g0, const float* __restrict__ be0,
           const float* __restrict__ g1, const float* __restrict__ be1,
           const float* __restrict__ g2, const float* __restrict__ be2,
           const float* __restrict__ g3, const float* __restrict__ be3,
           float* __restrict__ out)
{
    __shared__ SM sm;
    const int tid = threadIdx.x;
    const int b   = blockIdx.x * NTHR + tid;   // one thread per batch row

    // register-resident state
    float x0 = 100.f, x1a = 1.f, x1b = 1.f;
    float y0 = y0i[0], y1a = y1i[0], y1b = y1i[1];
    float z00 = z0i[0], z01 = z0i[1];
    float z10 = z1i[0], z11 = z1i[1], z12 = z1i[2], z13 = z1i[3];

    if (tid == 0) {
        sm.sc[0] = 100.f; sm.sc[1] = 1.f; sm.sc[2] = 1.f;
        sm.sc[3] = y0;    sm.sc[4] = y1a; sm.sc[5] = y1b;
    }
    __syncthreads();

    const float2* Wv = (const float2*)W;       // W is (B,T,2) -> float2 rows
    float2 wprev = Wv[b * TT];
    float s0 = 0.f, s1 = 0.f, dw0 = 0.f, dw1 = 0.f;
    unsigned bid_ = 0;

    for (int t = 0; t < NSTEP; ++t) {
        // per-thread inputs:  S is (B,2,T)
        s0 = __ldg(&S[b * (2*TT) + t]);
        s1 = __ldg(&S[b * (2*TT) + TT + t]);
        float2 wc = Wv[b * TT + t + 1];
        dw0 = wc.x - wprev.x; dw1 = wc.y - wprev.y; wprev = wc;

        // ---- Euler step for x0, then y/x1 updates ----
        float aV  = 0.025f * (s0 + s1);
        float ad  = 0.02f  * (s0 * x1a + s1 * x1b);
        float sx1 = x1a + x1b;
        float d0  = 0.1f * s0 * x0 + 0.03f * s0 * sx1;
        float d1  = 0.1f * s1 * x0 + 0.03f * s1 * sx1;
        float x0n = x0 + (aV * x0 + ad) * DTs + d0 * dw0 + d1 * dw1;

        float f0   = -0.05f * y0 + 0.01f * x0n;
        float y0n  = y0 - f0 * DTs + z00 * dw0 + z01 * dw1;
        float y1an = y1a + 0.05f * y1a * DTs + z10 * dw0 + z11 * dw1;
        float y1bn = y1b + 0.05f * y1b * DTs + z12 * dw0 + z13 * dw1;
        float x1an = x1a - y1an * DTs;
        float x1bn = x1b - y1bn * DTs;
        x0 = x0n; x1a = x1an; x1b = x1bn; y0 = y0n; y1a = y1an; y1b = y1bn;

        float zin[6] = {x0n, x1an, x1bn, y0n, y1an, y1bn};

        // ---- phase A: shifted 1st+2nd moments of zin (27 values) ----
        float r[6], vals[27];
#pragma unroll
        for (int k = 0; k < 6; k++) { r[k] = zin[k] - sm.sc[k]; vals[k] = r[k]; }
        {
            int p = 6;
#pragma unroll
            for (int k = 0; k < 6; k++)
#pragma unroll
                for (int l = k; l < 6; l++) vals[p++] = r[k] * r[l];
        }
        int buf = bid_ & 1;
        block_part<27>(vals, buf, tid, sm);

        // stage this step's params while peer blocks arrive
        if (tid < 144) sm.sp[OW2 + tid] = W2[t*144 + tid];
        if (tid < 72)  { sm.sp[OW1 + tid] = W1[t*72 + tid];
                         sm.sp[OW3 + tid] = W3[t*72 + tid]; }
        if (tid < 12)  { sm.sp[OG1 + tid] = g1[t*12 + tid];
                         sm.sp[OBE1 + tid] = be1[t*12 + tid];
                         sm.sp[OG2 + tid] = g2[t*12 + tid];
                         sm.sp[OBE2 + tid] = be2[t*12 + tid]; }
        if (tid < 6)   { sm.sp[OB3 + tid]  = b3[t*6 + tid];
                         sm.sp[OG0 + tid]  = g0[t*6 + tid];
                         sm.sp[OBE0 + tid] = be0[t*6 + tid];
                         sm.sp[OG3 + tid]  = g3[t*6 + tid];
                         sm.sp[OBE3 + tid] = be3[t*6 + tid]; }
        ++bid_;
        grid_barrier(bid_ * NBLK);
        combine<27>(buf, tid, sm);

        // BN0 stats + analytic BN1 stats
        if (tid < 6) {
            float md = sm.ssum[tid] * INVB;
            sm.smdev[tid] = md;
            sm.sM[tid] = sm.sc[tid] + md;
        }
        __syncthreads();
        if (tid < 21) {
            sm.sCov[tid] = sm.ssum[6 + tid] * INVB
                         - sm.smdev[cK[tid]] * sm.smdev[cL[tid]];
        } else if (tid >= 32 && tid < 44) {
            int j = tid - 32; float m = 0.f;
#pragma unroll
            for (int k = 0; k < 6; k++) m += sm.sp[OBE0 + k] * sm.sp[OW1 + k*12 + j];
            sm.sMean1[j] = m;
        }
        __syncthreads();
        if (tid < 6)
            sm.sA0[tid] = sm.sp[OG0 + tid] * rsqrtf(sm.sCov[cidx(tid, tid)] + EPSs);
        __syncthreads();
        if (tid < 12) {
            float wv[6];
#pragma unroll
            for (int k = 0; k < 6; k++) wv[k] = sm.sA0[k] * sm.sp[OW1 + k*12 + tid];
            float var = 0.f;
#pragma unroll
            for (int k = 0; k < 6; k++) {
                var += wv[k] * wv[k] * sm.sCov[cidx(k, k)];
#pragma unroll
                for (int l = k + 1; l < 6; l++)
                    var += 2.f * wv[k] * wv[l] * sm.sCov[cidx(k, l)];
            }
            sm.sInv1[tid] = sm.sp[OG1 + tid] * rsqrtf(var + EPSs);
        } else if (tid >= 32 && tid < 38) {
            sm.sc[tid - 32] = sm.sM[tid - 32];   // shift for next step
        }
        __syncthreads();

        // ---- BN0 -> layer1 -> BN1 -> relu (per thread) ----
        float hn[6];
#pragma unroll
        for (int k = 0; k < 6; k++)
            hn[k] = sm.sA0[k] * (zin[k] - sm.sM[k]) + sm.sp[OBE0 + k];
        float h1[12];
#pragma unroll
        for (int j = 0; j < 12; j++) {
            float u = 0.f;
#pragma unroll
            for (int k = 0; k < 6; k++) u += hn[k] * sm.sp[OW1 + k*12 + j];
            u = sm.sInv1[j] * (u - sm.sMean1[j]) + sm.sp[OBE1 + j];
            h1[j] = fmaxf(u, 0.f);
        }

        // ---- layer2 pre-activation + phase B stats ----
        float u2[12];
#pragma unroll
        for (int j = 0; j < 12; j++) {
            float u = 0.f;
#pragma unroll
            for (int k = 0; k < 12; k++) u += h1[k] * sm.sp[OW2 + k*12 + j];
            u2[j] = u;
        }
        float vals2[24];
#pragma unroll
        for (int j = 0; j < 12; j++) { vals2[j] = u2[j]; vals2[12 + j] = u2[j] * u2[j]; }
        buf = bid_ & 1;
        block_part<24>(vals2, buf, tid, sm);
        ++bid_;
        grid_barrier(bid_ * NBLK);
        combine<24>(buf, tid, sm);
        if (tid < 12) {
            float m = sm.ssum[tid] * INVB;
            float v = sm.ssum[12 + tid] * INVB - m * m;
            sm.sMean2[tid] = m;
            sm.sInv2[tid] = sm.sp[OG2 + tid] * rsqrtf(v + EPSs);
        }
        __syncthreads();

        // ---- BN2 -> relu -> layer3 + phase C stats ----
        float h2[12];
#pragma unroll
        for (int j = 0; j < 12; j++)
            h2[j] = fmaxf(sm.sInv2[j] * (u2[j] - sm.sMean2[j]) + sm.sp[OBE2 + j], 0.f);
        float u3[6];
#pragma unroll
        for (int j = 0; j < 6; j++) {
            float u = sm.sp[OB3 + j];
#pragma unroll
            for (int k = 0; k < 12; k++) u += h2[k] * sm.sp[OW3 + k*6 + j];
            u3[j] = u;
        }
        float vals3[12];
#pragma unroll
        for (int j = 0; j < 6; j++) { vals3[j] = u3[j]; vals3[6 + j] = u3[j] * u3[j]; }
        buf = bid_ & 1;
        block_part<12>(vals3, buf, tid, sm);
        ++bid_;
        grid_barrier(bid_ * NBLK);
        combine<12>(buf, tid, sm);
        if (tid < 6) {
            float m = sm.ssum[tid] * INVB;
            float v = sm.ssum[6 + tid] * INVB - m * m;
            sm.sMean3[tid] = m;
            sm.sInv3[tid] = sm.sp[OG3 + tid] * rsqrtf(v + EPSs);
        }
        __syncthreads();

        // ---- BN3 -> new z0, z1 ----
        float h3[6];
#pragma unroll
        for (int j = 0; j < 6; j++)
            h3[j] = sm.sInv3[j] * (u3[j] - sm.sMean3[j]) + sm.sp[OBE3 + j];
        z00 = h3[0]; z01 = h3[1];
        z10 = h3[2]; z11 = h3[3]; z12 = h3[4]; z13 = h3[5];
    }

    // ---- final half-step (reuses last step's s, dw) ----
    {
        float aV  = 0.025f * (s0 + s1);
        float ad  = 0.02f  * (s0 * x1a + s1 * x1b);
        float sx1 = x1a + x1b;
        float d0  = 0.1f * s0 * x0 + 0.03f * s0 * sx1;
        float d1  = 0.1f * s1 * x0 + 0.03f * s1 * sx1;
        float x0f = x0 + (aV * x0 + ad) * DTs + d0 * dw0 + d1 * dw1;

        float f0   = -0.05f * y0 + 0.01f * x0;   // note: uses x0, not x0f
        float y0f  = y0 - f0 * DTs + z00 * dw0 + z01 * dw1;
        float y1af = y1a + 0.05f * y1a * DTs + z10 * dw0 + z11 * dw1;
        float y1bf = y1b + 0.05f * y1b * DTs + z12 * dw0 + z13 * dw1;
        float x1af = x1a - y1af * DTs;
        float x1bf = x1b - y1bf * DTs;

        // output: concat of (x0f[B,1], x1f[B,2], y0f[B,1], y1f[B,2])
        out[b]              = x0f;
        out[NB + 2*b]       = x1af;
        out[NB + 2*b + 1]   = x1bf;
        out[3*NB + b]       = y0f;
        out[4*NB + 2*b]     = y1af;
        out[4*NB + 2*b + 1] = y1bf;
    }
}

extern "C" void kernel_launch(void* const* d_in, const int* in_sizes, int n_in,
                              void* d_out, int out_size) {
    const float* W   = (const float*)d_in[0];
    const float* S   = (const float*)d_in[1];
    const float* y0i = (const float*)d_in[2];
    const float* y1i = (const float*)d_in[3];
    const float* z0i = (const float*)d_in[4];
    const float* z1i = (const float*)d_in[5];
    const float* W1  = (const float*)d_in[6];
    const float* W2  = (const float*)d_in[7];
    const float* W3  = (const float*)d_in[8];
    const float* b3  = (const float*)d_in[9];
    const float* g0  = (const float*)d_in[10];
    const float* be0 = (const float*)d_in[11];
    const float* g1  = (const float*)d_in[12];
    const float* be1 = (const float*)d_in[13];
    const float* g2  = (const float*)d_in[14];
    const float* be2 = (const float*)d_in[15];
    const float* g3  = (const float*)d_in[16];
    const float* be3 = (const float*)d_in[17];
    float* out = (float*)d_out;

    init_bar<<<1, 1>>>();

    // Cooperative launch: driver validates that all NBLK blocks can be
    // co-resident; fails fast with an error instead of deadlocking if not.
    void* args[] = {
        (void*)&W, (void*)&S, (void*)&y0i, (void*)&y1i, (void*)&z0i,
        (void*)&z1i, (void*)&W1, (void*)&W2, (void*)&W3, (void*)&b3,
        (void*)&g0, (void*)&be0, (void*)&g1, (void*)&be1, (void*)&g2,
        (void*)&be2, (void*)&g3, (void*)&be3, (void*)&out
    };
    cudaLaunchCooperativeKernel((const void*)sde_kernel,
                                dim3(NBLK), dim3(NTHR), args, 0, 0);
}